// round 11
// baseline (speedup 1.0000x reference)
#include <cuda_runtime.h>
#include <cstdint>

// ---------------------------------------------------------------------------
// Problem constants
// ---------------------------------------------------------------------------
#define N_R       2000
#define N_P       1512
#define M_TOT     3512
#define SIZE_R    3000
#define FUN_IN    5603
#define ATT_H     2048
#define FUN_H     4096
#define DFEAT     512
#define BATCH     8192
#define KP_ATT    3008
#define KP_FUN    5616

#define EP_OFF    (N_R * DFEAT)
#define OUT2_OFF  (EP_OFF + N_P * DFEAT)
#define FLAT_OFF  (OUT2_OFF + BATCH * 2)

// ---------------------------------------------------------------------------
// packed f32x2 helpers (FFMA2)
// ---------------------------------------------------------------------------
typedef unsigned long long ull;
#define PACKF2(d, lo, hi) asm("mov.b64 %0, {%1, %2};" : "=l"(d) : "f"(lo), "f"(hi))
#define FMAF2(acc, a, b)  asm("fma.rn.f32x2 %0, %1, %2, %0;" : "+l"(acc) : "l"(a), "l"(b))
#define UNPKF2(lo, hi, v) asm("mov.b64 {%0, %1}, %2;" : "=f"(lo), "=f"(hi) : "l"(v))

// ---------------------------------------------------------------------------
// fp32 scratch
// ---------------------------------------------------------------------------
__device__ __align__(256) float gAatt[(size_t)M_TOT * KP_ATT];
__device__ __align__(256) float gAfun[(size_t)M_TOT * KP_FUN];
__device__ __align__(256) float gHa[(size_t)M_TOT * ATT_H];
__device__ __align__(256) float gHf[(size_t)M_TOT * FUN_H];

// ---------------------------------------------------------------------------
// concat + pad copy
// ---------------------------------------------------------------------------
__global__ void convA_f32(const float* __restrict__ A0, const float* __restrict__ A1,
                          int split, int K, int Kpad, float* __restrict__ dst)
{
    const int k = blockIdx.x * 256 + threadIdx.x;
    const int m = blockIdx.y;
    if (k >= Kpad) return;
    float x = 0.0f;
    if (k < K)
        x = (m < split) ? A0[(size_t)m * K + k] : A1[(size_t)(m - split) * K + k];
    dst[(size_t)m * Kpad + k] = x;
}

// ---------------------------------------------------------------------------
// FFMA2 SGEMM, dual-problem fused launch.
//   Problem p (p=0,1): C = act( Ap(M,ldap) @ Wp(Kp,Np) + biasp )
//   1D grid: first nbx0*nby blocks -> problem 0, rest -> problem 1.
// EPI 0: gelu -> H[gm*ldh+gn];  EPI 1: sigmoid -> scatter into d_out
// ---------------------------------------------------------------------------
template <int BN, int TN, int EPI>
__global__ __launch_bounds__(256, 2)
void sgemm_dual(int nbx0, int nbx1, int nby, int M, float* __restrict__ outp,
                const float* __restrict__ A0p, int lda0, int Kpad0, int Kreal0,
                const float* __restrict__ W0, int N0, const float* __restrict__ bias0,
                float* __restrict__ H0, int ldh0, int colOff0,
                const float* __restrict__ A1p, int lda1, int Kpad1, int Kreal1,
                const float* __restrict__ W1, int N1, const float* __restrict__ bias1,
                float* __restrict__ H1, int ldh1, int colOff1)
{
    constexpr int BM = 128, BK = 16, TM = 8;
    constexpr int ASTR = BM + 4;
    constexpr int NF = BN / 64;
    constexpr int TP = TN / 2;
    static_assert((BM / TM) * (BN / TN) == 256, "256 threads");

    __shared__ float As[2][BK * ASTR];
    __shared__ float Bs[2][BK * BN];

    // ---- select problem ----
    const int bid = blockIdx.x;
    const int b0c = nbx0 * nby;
    const float *A, *W, *bias; float* H;
    int lda, Kpad, Kreal, N, ldh, colOff, bx, by;
    if (bid < b0c) {
        bx = bid % nbx0; by = bid / nbx0;
        A = A0p; lda = lda0; Kpad = Kpad0; Kreal = Kreal0;
        W = W0; N = N0; bias = bias0; H = H0; ldh = ldh0; colOff = colOff0;
    } else {
        const int r = bid - b0c;
        bx = r % nbx1; by = r / nbx1;
        A = A1p; lda = lda1; Kpad = Kpad1; Kreal = Kreal1;
        W = W1; N = N1; bias = bias1; H = H1; ldh = ldh1; colOff = colOff1;
    }

    const int tid = threadIdx.x;
    const int tx  = tid & 15;
    const int ty  = tid >> 4;
    const int bm0 = by * BM;
    const int bn0 = bx * BN;

    const int arow = tid >> 1;
    const int ak   = (tid & 1) * 8;
    int gmA = bm0 + arow; if (gmA >= M) gmA = M - 1;
    const float* Aptr = A + (size_t)gmA * lda + ak;

    const int bkr = tid >> 4;
    const int bnf = tid & 15;

    float4 ra0, ra1, rb[NF];

    ull acc2[TM][TP];
#pragma unroll
    for (int i = 0; i < TM; ++i)
#pragma unroll
        for (int j = 0; j < TP; ++j) acc2[i][j] = 0ULL;

    auto ldg = [&](int kt) {
        ra0 = *reinterpret_cast<const float4*>(Aptr + kt);
        ra1 = *reinterpret_cast<const float4*>(Aptr + kt + 4);
        const int gk = kt + bkr;
        if (gk < Kreal) {
            const float* Wr = W + (size_t)gk * N + bn0;
#pragma unroll
            for (int f = 0; f < NF; ++f)
                rb[f] = *reinterpret_cast<const float4*>(Wr + (bnf + f * 16) * 4);
        } else {
#pragma unroll
            for (int f = 0; f < NF; ++f) rb[f] = make_float4(0.f, 0.f, 0.f, 0.f);
        }
    };
    auto sts = [&](int b) {
        float av[8] = {ra0.x, ra0.y, ra0.z, ra0.w, ra1.x, ra1.y, ra1.z, ra1.w};
#pragma unroll
        for (int i = 0; i < 8; ++i)
            As[b][(ak + i) * ASTR + arow] = av[i];
#pragma unroll
        for (int f = 0; f < NF; ++f)
            *reinterpret_cast<float4*>(&Bs[b][bkr * BN + (bnf + f * 16) * 4]) = rb[f];
    };

    const int nc = Kpad / BK;
    ldg(0);
    sts(0);
    __syncthreads();

    for (int c = 0; c < nc; ++c) {
        if (c + 1 < nc) ldg((c + 1) * BK);
        const int cur = c & 1;
#pragma unroll
        for (int k = 0; k < BK; ++k) {
            float a[TM];
            ull  b2[TP];
            *reinterpret_cast<float4*>(&a[0]) =
                *reinterpret_cast<const float4*>(&As[cur][k * ASTR + ty * 4]);
            *reinterpret_cast<float4*>(&a[4]) =
                *reinterpret_cast<const float4*>(&As[cur][k * ASTR + ty * 4 + 64]);
            {
                ulonglong2 q0 = *reinterpret_cast<const ulonglong2*>(
                    &Bs[cur][k * BN + tx * 4]);
                b2[0] = q0.x; b2[1] = q0.y;
                if constexpr (TN == 8) {
                    ulonglong2 q1 = *reinterpret_cast<const ulonglong2*>(
                        &Bs[cur][k * BN + tx * 4 + 64]);
                    b2[2] = q1.x; b2[3] = q1.y;
                }
            }
#pragma unroll
            for (int i = 0; i < TM; ++i) {
                ull a2; PACKF2(a2, a[i], a[i]);
#pragma unroll
                for (int j = 0; j < TP; ++j)
                    FMAF2(acc2[i][j], a2, b2[j]);
            }
        }
        if (c + 1 < nc) sts((c + 1) & 1);
        __syncthreads();
    }

    // ---- epilogue ----
#pragma unroll
    for (int i = 0; i < TM; ++i) {
        const int gm = bm0 + ty * 4 + (i & 3) + (i >> 2) * 64;
        if (gm >= M) continue;
#pragma unroll
        for (int j = 0; j < TP; ++j) {
            const int gn = bn0 + tx * 4 + (j & 1) * 2 + (j >> 1) * 64;
            float c0, c1;
            UNPKF2(c0, c1, acc2[i][j]);
            const float v0 = c0 + __ldg(bias + gn);
            const float v1 = c1 + __ldg(bias + gn + 1);
            if constexpr (EPI == 0) {
                H[(size_t)gm * ldh + gn]     =
                    0.5f * v0 * (1.0f + erff(v0 * 0.70710678118654752f));
                H[(size_t)gm * ldh + gn + 1] =
                    0.5f * v1 * (1.0f + erff(v1 * 0.70710678118654752f));
            } else {
                float* dst = (gm < N_R)
                                 ? (outp + (size_t)gm * DFEAT + colOff + gn)
                                 : (outp + EP_OFF + (size_t)(gm - N_R) * DFEAT + colOff + gn);
                dst[0] = 1.0f / (1.0f + expf(-v0));
                dst[1] = 1.0f / (1.0f + expf(-v1));
            }
        }
    }
}

// ---------------------------------------------------------------------------
// CNN head — conv1 register-cached; conv2 oc-pair FFMA2 with prepacked
// dual weights in smem; fast tanh.
// smem layout (floats):
//  s_x[2*516] | s_w1[240] | s_b1[16] | s_b2[32] | s_w2p[3840 ull = 7680 f]
//  | s_p1[16*2*260] | s_red[16]
// ---------------------------------------------------------------------------
#define SMX    0
#define SMW1   (SMX  + 2 * 516)            // 1032
#define SMB1   (SMW1 + 240)                // 1272
#define SMB2   (SMB1 + 16)                 // 1288
#define SMW2P  (SMB2 + 32)                 // 1320 (even -> 8B aligned)
#define SMP1   (SMW2P + 7680)              // 9000
#define SMRED  (SMP1 + 16 * 2 * 260)       // 17320
#define SMTOT  (SMRED + 16)                // 17336 floats = 69344 B

__global__ __launch_bounds__(256)
void conv_head_k(const float* __restrict__ w1, const float* __restrict__ b1,
                 const float* __restrict__ w2, const float* __restrict__ b2,
                 const int* __restrict__ idx,
                 const float* __restrict__ Wout, const float* __restrict__ bout,
                 float* __restrict__ out)
{
    extern __shared__ float smf[];
    float* s_x   = smf + SMX;
    float* s_w1  = smf + SMW1;
    float* s_b1  = smf + SMB1;
    float* s_b2  = smf + SMB2;
    ull*   s_w2p = reinterpret_cast<ull*>(smf + SMW2P);
    float* s_p1  = smf + SMP1;
    float* s_red = smf + SMRED;

    const int tid = threadIdx.x;
    const int b   = blockIdx.x;

    for (int i = tid; i < 2 * 516; i += 256) s_x[i] = 0.0f;
    for (int i = tid; i < 16 * 2 * 260; i += 256) s_p1[i] = 0.0f;
    for (int i = tid; i < 240; i += 256) s_w1[i] = w1[i];
    // prepack conv2 weights as (w_{2op}, w_{2op+1}) pairs; linear index i
    // decomposes as ((op*16+ic)*3+kh)*5+kw
    for (int i = tid; i < 3840; i += 256) {
        const int kw = i % 5;
        int r = i / 5;
        const int kh = r % 3; r /= 3;
        const int ic = r % 16;
        const int op = r / 16;
        const float we = w2[(((2 * op) * 16 + ic) * 3 + kh) * 5 + kw];
        const float wo = w2[(((2 * op + 1) * 16 + ic) * 3 + kh) * 5 + kw];
        reinterpret_cast<float2*>(s_w2p)[i] = make_float2(we, wo);
    }
    if (tid < 16) s_b1[tid] = b1[tid];
    if (tid >= 32 && tid < 64) s_b2[tid - 32] = b2[tid - 32];

    const int id   = idx[b];
    const int r_no = id / 1512;
    const int p_no = id - r_no * 1512;
    __syncthreads();

    for (int c = tid; c < DFEAT; c += 256) {
        s_x[2 + c]        = out[(size_t)r_no * DFEAT + c];
        s_x[516 + 2 + c]  = out[EP_OFF + (size_t)p_no * DFEAT + c];
    }
    __syncthreads();

    // ---- conv1 + leaky + avgpool -> s_p1 (16,2,256), register-cached ----
    for (int j = tid; j < 16 * 2 * 256; j += 256) {
        const int oc = j >> 9;            // warp-uniform
        const int ph = (j >> 8) & 1;      // warp-uniform
        const int pw = j & 255;
        float w[15];
#pragma unroll
        for (int i = 0; i < 15; ++i) w[i] = s_w1[oc * 15 + i];
        float x0[6], x1[6];
        {
            const float* r0 = s_x + 2 * pw;
            const float* r1 = s_x + 516 + 2 * pw;
#pragma unroll
            for (int i = 0; i < 6; i += 2) {
                float2 u = *reinterpret_cast<const float2*>(r0 + i);
                x0[i] = u.x; x0[i + 1] = u.y;
                float2 v = *reinterpret_cast<const float2*>(r1 + i);
                x1[i] = v.x; x1[i + 1] = v.y;
            }
        }
        const float bv = s_b1[oc];
        float sum = 0.0f;
#pragma unroll
        for (int dh = 0; dh < 2; ++dh) {
            const int oh = 2 * ph + dh;
#pragma unroll
            for (int dw = 0; dw < 2; ++dw) {
                float c = 0.0f;
                const int kh0 = 2 - oh;        // kh for ih=0
#pragma unroll
                for (int ih = 0; ih < 2; ++ih) {
                    const int kh = kh0 + ih;
                    if (kh >= 0 && kh < 3) {
                        const float* xr = ih ? x1 : x0;
#pragma unroll
                        for (int kw = 0; kw < 5; ++kw)
                            c = fmaf(w[kh * 5 + kw], xr[dw + kw], c);
                    }
                }
                c += bv;
                sum += (c >= 0.0f) ? c : 0.01f * c;
            }
        }
        s_p1[(oc * 2 + ph) * 260 + 2 + pw] = 0.25f * sum;
    }
    __syncthreads();

    // ---- conv2 (oc-pair FFMA2) + maxpool + leaky + tanh + flat + out ----
    float ro0 = 0.0f, ro1 = 0.0f;
#pragma unroll
    for (int pass = 0; pass < 4; ++pass) {
        const int t    = tid + pass * 256;
        const int op   = t >> 6;          // 0..15 oc-pair (warp-uniform)
        const int ph   = (t >> 5) & 1;    // warp-uniform
        const int pwg  = t & 31;          // lane
        const int ow0  = pwg * 8;         // 8 conv-ow per thread

        ull accA2[8], accB2[8];
#pragma unroll
        for (int j = 0; j < 8; ++j) { accA2[j] = 0ULL; accB2[j] = 0ULL; }

        const int khA0 = 2 - 2 * ph;
#pragma unroll
        for (int ic = 0; ic < 16; ++ic) {
#pragma unroll
            for (int ih = 0; ih < 2; ++ih) {
                const float* rowp = s_p1 + (ic * 2 + ih) * 260 + ow0;
                float4 u0 = *reinterpret_cast<const float4*>(rowp);
                float4 u1 = *reinterpret_cast<const float4*>(rowp + 4);
                float4 u2 = *reinterpret_cast<const float4*>(rowp + 8);
                float in[12] = {u0.x, u0.y, u0.z, u0.w, u1.x, u1.y, u1.z, u1.w,
                                u2.x, u2.y, u2.z, u2.w};
                ull px[12];
#pragma unroll
                for (int s = 0; s < 12; ++s) PACKF2(px[s], in[s], in[s]);

                const ull* wbase = s_w2p + (op * 16 + ic) * 15;
                const int khA = ih + khA0;
                if (khA >= 0 && khA < 3) {
                    const ull* wr = wbase + khA * 5;
#pragma unroll
                    for (int kw = 0; kw < 5; ++kw) {
                        const ull wp = wr[kw];
#pragma unroll
                        for (int j = 0; j < 8; ++j)
                            FMAF2(accA2[j], wp, px[j + kw]);
                    }
                }
                const int khB = khA - 1;
                if (khB >= 0 && khB < 3) {
                    const ull* wr = wbase + khB * 5;
#pragma unroll
                    for (int kw = 0; kw < 5; ++kw) {
                        const ull wp = wr[kw];
#pragma unroll
                        for (int j = 0; j < 8; ++j)
                            FMAF2(accB2[j], wp, px[j + kw]);
                    }
                }
            }
        }
        // pool pairs (2p, 2p+1) across A/B rows; unpack oc-even/odd
        const float bve = s_b2[2 * op];
        const float bvo = s_b2[2 * op + 1];
#pragma unroll
        for (int p = 0; p < 4; ++p) {
            float a0e, a0o, a1e, a1o, b0e, b0o, b1e, b1o;
            UNPKF2(a0e, a0o, accA2[2 * p]);
            UNPKF2(a1e, a1o, accA2[2 * p + 1]);
            UNPKF2(b0e, b0o, accB2[2 * p]);
            UNPKF2(b1e, b1o, accB2[2 * p + 1]);
            const int pool_w = pwg * 4 + p;
#pragma unroll
            for (int e = 0; e < 2; ++e) {
                const float m = e ? fmaxf(fmaxf(a0o, a1o), fmaxf(b0o, b1o))
                                  : fmaxf(fmaxf(a0e, a1e), fmaxf(b0e, b1e));
                float v = m + (e ? bvo : bve);
                v = (v >= 0.0f) ? v : 0.01f * v;
                const float ex = __expf(2.0f * v);
                const float tv = __fdividef(ex - 1.0f, ex + 1.0f);
                const int f = (2 * op + e) * 256 + ph * 128 + pool_w;
                out[FLAT_OFF + (size_t)b * 8192 + f] = tv;
                ro0 = fmaf(tv, __ldg(Wout + 2 * f), ro0);
                ro1 = fmaf(tv, __ldg(Wout + 2 * f + 1), ro1);
            }
        }
    }

#pragma unroll
    for (int off = 16; off > 0; off >>= 1) {
        ro0 += __shfl_down_sync(0xffffffffu, ro0, off);
        ro1 += __shfl_down_sync(0xffffffffu, ro1, off);
    }
    const int warp = tid >> 5, lane = tid & 31;
    if (lane == 0) { s_red[warp] = ro0; s_red[8 + warp] = ro1; }
    __syncthreads();
    if (tid == 0) {
        float a = 0.0f, c = 0.0f;
#pragma unroll
        for (int i = 0; i < 8; ++i) { a += s_red[i]; c += s_red[8 + i]; }
        out[OUT2_OFF + (size_t)b * 2 + 0] = a + bout[0];
        out[OUT2_OFF + (size_t)b * 2 + 1] = c + bout[1];
    }
}

// ---------------------------------------------------------------------------
extern "C" void kernel_launch(void* const* d_in, const int* in_sizes, int n_in,
                              void* d_out, int out_size)
{
    const float* r_att   = (const float*)d_in[0];
    const float* p_att   = (const float*)d_in[1];
    const float* r_fun   = (const float*)d_in[2];
    const float* p_fun   = (const float*)d_in[3];
    const int*   idx     = (const int*)  d_in[4];
    const float* W_att1  = (const float*)d_in[5];
    const float* b_att1  = (const float*)d_in[6];
    const float* W_att2  = (const float*)d_in[7];
    const float* b_att2  = (const float*)d_in[8];
    const float* W_fun1  = (const float*)d_in[9];
    const float* b_fun1  = (const float*)d_in[10];
    const float* W_fun2  = (const float*)d_in[11];
    const float* b_fun2  = (const float*)d_in[12];
    const float* conv1_w = (const float*)d_in[13];
    const float* conv1_b = (const float*)d_in[14];
    const float* conv2_w = (const float*)d_in[15];
    const float* conv2_b = (const float*)d_in[16];
    const float* W_out   = (const float*)d_in[17];
    const float* b_out   = (const float*)d_in[18];
    float* out = (float*)d_out;

    float *pAa, *pAf, *pHa, *pHf;
    cudaGetSymbolAddress((void**)&pAa, gAatt);
    cudaGetSymbolAddress((void**)&pAf, gAfun);
    cudaGetSymbolAddress((void**)&pHa, gHa);
    cudaGetSymbolAddress((void**)&pHf, gHf);

    const size_t conv_smem = SMTOT * sizeof(float);
    cudaFuncSetAttribute(conv_head_k, cudaFuncAttributeMaxDynamicSharedMemorySize,
                         (int)conv_smem);

    convA_f32<<<dim3((KP_FUN + 255) / 256, M_TOT), 256>>>(r_fun, p_fun, N_R, FUN_IN, KP_FUN, pAf);
    convA_f32<<<dim3((KP_ATT + 255) / 256, M_TOT), 256>>>(r_att, p_att, N_R, SIZE_R, KP_ATT, pAa);

    const int nby = (M_TOT + 127) / 128;   // 28

    // layer1 fused: att1 (16x28) + fun1 (32x28) = 1344 blocks
    sgemm_dual<128, 8, 0><<<(ATT_H / 128 + FUN_H / 128) * nby, 256>>>(
        ATT_H / 128, FUN_H / 128, nby, M_TOT, out,
        pAa, KP_ATT, KP_ATT, SIZE_R, W_att1, ATT_H, b_att1, pHa, ATT_H, 0,
        pAf, KP_FUN, KP_FUN, FUN_IN, W_fun1, FUN_H, b_fun1, pHf, FUN_H, 0);

    // layer2 fused: att2 (4x28) + fun2 (4x28) = 224 blocks
    sgemm_dual<64, 4, 1><<<(256 / 64 + 256 / 64) * nby, 256>>>(
        256 / 64, 256 / 64, nby, M_TOT, out,
        pHa, ATT_H, ATT_H, ATT_H, W_att2, 256, b_att2, nullptr, 0, 0,
        pHf, FUN_H, FUN_H, FUN_H, W_fun2, 256, b_fun2, nullptr, 0, 256);

    conv_head_k<<<BATCH, 256, conv_smem>>>(
        conv1_w, conv1_b, conv2_w, conv2_b, idx, W_out, b_out, out);

    (void)in_sizes; (void)n_in; (void)out_size;
}

// round 12
// speedup vs baseline: 1.2262x; 1.2262x over previous
#include <cuda_runtime.h>
#include <cstdint>

// ---------------------------------------------------------------------------
// Problem constants
// ---------------------------------------------------------------------------
#define N_R       2000
#define N_P       1512
#define M_TOT     3512
#define SIZE_R    3000
#define FUN_IN    5603
#define ATT_H     2048
#define FUN_H     4096
#define DFEAT     512
#define BATCH     8192
#define KP_ATT    3008
#define KP_FUN    5616

#define EP_OFF    (N_R * DFEAT)
#define OUT2_OFF  (EP_OFF + N_P * DFEAT)
#define FLAT_OFF  (OUT2_OFF + BATCH * 2)

#define NSPLIT    4

// ---------------------------------------------------------------------------
// packed f32x2 helpers (FFMA2)
// ---------------------------------------------------------------------------
typedef unsigned long long ull;
#define PACKF2(d, lo, hi) asm("mov.b64 %0, {%1, %2};" : "=l"(d) : "f"(lo), "f"(hi))
#define FMAF2(acc, a, b)  asm("fma.rn.f32x2 %0, %1, %2, %0;" : "+l"(acc) : "l"(a), "l"(b))
#define UNPKF2(lo, hi, v) asm("mov.b64 {%0, %1}, %2;" : "=f"(lo), "=f"(hi) : "l"(v))

// ---------------------------------------------------------------------------
// fp32 scratch.  gAfun doubles as the split-K partial buffer for layer 2
// (it is only read by layer 1, which completes before layer 2 launches).
// ---------------------------------------------------------------------------
__device__ __align__(256) float gAatt[(size_t)M_TOT * KP_ATT];
__device__ __align__(256) float gAfun[(size_t)M_TOT * KP_FUN];
__device__ __align__(256) float gHa[(size_t)M_TOT * ATT_H];
__device__ __align__(256) float gHf[(size_t)M_TOT * FUN_H];

// ---------------------------------------------------------------------------
// concat + pad copy
// ---------------------------------------------------------------------------
__global__ void convA_f32(const float* __restrict__ A0, const float* __restrict__ A1,
                          int split, int K, int Kpad, float* __restrict__ dst)
{
    const int k = blockIdx.x * 256 + threadIdx.x;
    const int m = blockIdx.y;
    if (k >= Kpad) return;
    float x = 0.0f;
    if (k < K)
        x = (m < split) ? A0[(size_t)m * K + k] : A1[(size_t)(m - split) * K + k];
    dst[(size_t)m * Kpad + k] = x;
}

// ---------------------------------------------------------------------------
// FFMA2 SGEMM, dual-problem fused launch (layer 1: gelu -> H)
// ---------------------------------------------------------------------------
template <int BN, int TN>
__global__ __launch_bounds__(256, 2)
void sgemm_dual(int nbx0, int nbx1, int nby, int M,
                const float* __restrict__ A0p, int lda0, int Kpad0, int Kreal0,
                const float* __restrict__ W0, int N0, const float* __restrict__ bias0,
                float* __restrict__ H0, int ldh0,
                const float* __restrict__ A1p, int lda1, int Kpad1, int Kreal1,
                const float* __restrict__ W1, int N1, const float* __restrict__ bias1,
                float* __restrict__ H1, int ldh1)
{
    constexpr int BM = 128, BK = 16, TM = 8;
    constexpr int ASTR = BM + 4;
    constexpr int NF = BN / 64;
    constexpr int TP = TN / 2;
    static_assert((BM / TM) * (BN / TN) == 256, "256 threads");

    __shared__ float As[2][BK * ASTR];
    __shared__ float Bs[2][BK * BN];

    const int bid = blockIdx.x;
    const int b0c = nbx0 * nby;
    const float *A, *W, *bias; float* H;
    int lda, Kpad, Kreal, N, ldh, bx, by;
    if (bid < b0c) {
        bx = bid % nbx0; by = bid / nbx0;
        A = A0p; lda = lda0; Kpad = Kpad0; Kreal = Kreal0;
        W = W0; N = N0; bias = bias0; H = H0; ldh = ldh0;
    } else {
        const int r = bid - b0c;
        bx = r % nbx1; by = r / nbx1;
        A = A1p; lda = lda1; Kpad = Kpad1; Kreal = Kreal1;
        W = W1; N = N1; bias = bias1; H = H1; ldh = ldh1;
    }

    const int tid = threadIdx.x;
    const int tx  = tid & 15;
    const int ty  = tid >> 4;
    const int bm0 = by * BM;
    const int bn0 = bx * BN;

    const int arow = tid >> 1;
    const int ak   = (tid & 1) * 8;
    int gmA = bm0 + arow; if (gmA >= M) gmA = M - 1;
    const float* Aptr = A + (size_t)gmA * lda + ak;

    const int bkr = tid >> 4;
    const int bnf = tid & 15;

    float4 ra0, ra1, rb[NF];

    ull acc2[TM][TP];
#pragma unroll
    for (int i = 0; i < TM; ++i)
#pragma unroll
        for (int j = 0; j < TP; ++j) acc2[i][j] = 0ULL;

    auto ldg = [&](int kt) {
        ra0 = *reinterpret_cast<const float4*>(Aptr + kt);
        ra1 = *reinterpret_cast<const float4*>(Aptr + kt + 4);
        const int gk = kt + bkr;
        if (gk < Kreal) {
            const float* Wr = W + (size_t)gk * N + bn0;
#pragma unroll
            for (int f = 0; f < NF; ++f)
                rb[f] = *reinterpret_cast<const float4*>(Wr + (bnf + f * 16) * 4);
        } else {
#pragma unroll
            for (int f = 0; f < NF; ++f) rb[f] = make_float4(0.f, 0.f, 0.f, 0.f);
        }
    };
    auto sts = [&](int b) {
        float av[8] = {ra0.x, ra0.y, ra0.z, ra0.w, ra1.x, ra1.y, ra1.z, ra1.w};
#pragma unroll
        for (int i = 0; i < 8; ++i)
            As[b][(ak + i) * ASTR + arow] = av[i];
#pragma unroll
        for (int f = 0; f < NF; ++f)
            *reinterpret_cast<float4*>(&Bs[b][bkr * BN + (bnf + f * 16) * 4]) = rb[f];
    };

    const int nc = Kpad / BK;
    ldg(0);
    sts(0);
    __syncthreads();

    for (int c = 0; c < nc; ++c) {
        if (c + 1 < nc) ldg((c + 1) * BK);
        const int cur = c & 1;
#pragma unroll
        for (int k = 0; k < BK; ++k) {
            float a[TM];
            ull  b2[TP];
            *reinterpret_cast<float4*>(&a[0]) =
                *reinterpret_cast<const float4*>(&As[cur][k * ASTR + ty * 4]);
            *reinterpret_cast<float4*>(&a[4]) =
                *reinterpret_cast<const float4*>(&As[cur][k * ASTR + ty * 4 + 64]);
            {
                ulonglong2 q0 = *reinterpret_cast<const ulonglong2*>(
                    &Bs[cur][k * BN + tx * 4]);
                b2[0] = q0.x; b2[1] = q0.y;
                if constexpr (TN == 8) {
                    ulonglong2 q1 = *reinterpret_cast<const ulonglong2*>(
                        &Bs[cur][k * BN + tx * 4 + 64]);
                    b2[2] = q1.x; b2[3] = q1.y;
                }
            }
#pragma unroll
            for (int i = 0; i < TM; ++i) {
                ull a2; PACKF2(a2, a[i], a[i]);
#pragma unroll
                for (int j = 0; j < TP; ++j)
                    FMAF2(acc2[i][j], a2, b2[j]);
            }
        }
        if (c + 1 < nc) sts((c + 1) & 1);
        __syncthreads();
    }

#pragma unroll
    for (int i = 0; i < TM; ++i) {
        const int gm = bm0 + ty * 4 + (i & 3) + (i >> 2) * 64;
        if (gm >= M) continue;
#pragma unroll
        for (int j = 0; j < TP; ++j) {
            const int gn = bn0 + tx * 4 + (j & 1) * 2 + (j >> 1) * 64;
            float c0, c1;
            UNPKF2(c0, c1, acc2[i][j]);
            const float v0 = c0 + __ldg(bias + gn);
            const float v1 = c1 + __ldg(bias + gn + 1);
            H[(size_t)gm * ldh + gn]     =
                0.5f * v0 * (1.0f + erff(v0 * 0.70710678118654752f));
            H[(size_t)gm * ldh + gn + 1] =
                0.5f * v1 * (1.0f + erff(v1 * 0.70710678118654752f));
        }
    }
}

// ---------------------------------------------------------------------------
// Layer-2 split-K GEMM (both problems, NSPLIT K-slices), raw partials to
// part[((p*NSPLIT+s)*M + gm)*256 + gn].  BM=128, BN=64, TN=4.
// ---------------------------------------------------------------------------
__global__ __launch_bounds__(256, 2)
void sgemm_splitk(int nby, int M, float* __restrict__ part,
                  const float* __restrict__ A0p, int lda0, int Kpad0,
                  const float* __restrict__ W0,
                  const float* __restrict__ A1p, int lda1, int Kpad1,
                  const float* __restrict__ W1)
{
    constexpr int BM = 128, BK = 16, TM = 8, BN = 64, TN = 4;
    constexpr int ASTR = BM + 4;
    constexpr int TP = TN / 2;
    constexpr int NBX = 256 / BN;            // 4
    constexpr int NLOC = 256;                // N per problem

    __shared__ float As[2][BK * ASTR];
    __shared__ float Bs[2][BK * BN];

    const int perprob = NSPLIT * NBX * nby;
    const int bid = blockIdx.x;
    const int p = (bid < perprob) ? 0 : 1;
    const int r = bid - p * perprob;
    const int s = r / (NBX * nby);
    const int rem = r % (NBX * nby);
    const int bx = rem % NBX;
    const int by = rem / NBX;

    const float* A  = p ? A1p : A0p;
    const float* W  = p ? W1  : W0;
    const int lda   = p ? lda1 : lda0;
    const int Kpad  = p ? Kpad1 : Kpad0;

    const int tid = threadIdx.x;
    const int tx  = tid & 15;
    const int ty  = tid >> 4;
    const int bm0 = by * BM;
    const int bn0 = bx * BN;

    const int arow = tid >> 1;
    const int ak   = (tid & 1) * 8;
    int gmA = bm0 + arow; if (gmA >= M) gmA = M - 1;
    const float* Aptr = A + (size_t)gmA * lda + ak;

    const int bkr = tid >> 4;
    const int bnf = tid & 15;

    float4 ra0, ra1, rb0;

    ull acc2[TM][TP];
#pragma unroll
    for (int i = 0; i < TM; ++i)
#pragma unroll
        for (int j = 0; j < TP; ++j) acc2[i][j] = 0ULL;

    auto ldg = [&](int kt) {
        ra0 = *reinterpret_cast<const float4*>(Aptr + kt);
        ra1 = *reinterpret_cast<const float4*>(Aptr + kt + 4);
        const int gk = kt + bkr;
        rb0 = *reinterpret_cast<const float4*>(W + (size_t)gk * NLOC + bn0 + bnf * 4);
    };
    auto sts = [&](int b) {
        float av[8] = {ra0.x, ra0.y, ra0.z, ra0.w, ra1.x, ra1.y, ra1.z, ra1.w};
#pragma unroll
        for (int i = 0; i < 8; ++i)
            As[b][(ak + i) * ASTR + arow] = av[i];
        *reinterpret_cast<float4*>(&Bs[b][bkr * BN + bnf * 4]) = rb0;
    };

    const int Kq = Kpad / NSPLIT;            // 512 or 1024 (BK-multiples)
    const int c0 = (s * Kq) / BK;
    const int c1 = ((s + 1) * Kq) / BK;

    ldg(c0 * BK);
    sts(0);
    __syncthreads();

    for (int c = c0; c < c1; ++c) {
        if (c + 1 < c1) ldg((c + 1) * BK);
        const int cur = (c - c0) & 1;
#pragma unroll
        for (int k = 0; k < BK; ++k) {
            float a[TM];
            ull  b2[TP];
            *reinterpret_cast<float4*>(&a[0]) =
                *reinterpret_cast<const float4*>(&As[cur][k * ASTR + ty * 4]);
            *reinterpret_cast<float4*>(&a[4]) =
                *reinterpret_cast<const float4*>(&As[cur][k * ASTR + ty * 4 + 64]);
            ulonglong2 q0 = *reinterpret_cast<const ulonglong2*>(
                &Bs[cur][k * BN + tx * 4]);
            b2[0] = q0.x; b2[1] = q0.y;
#pragma unroll
            for (int i = 0; i < TM; ++i) {
                ull a2; PACKF2(a2, a[i], a[i]);
#pragma unroll
                for (int j = 0; j < TP; ++j)
                    FMAF2(acc2[i][j], a2, b2[j]);
            }
        }
        if (c + 1 < c1) sts((c - c0 + 1) & 1);
        __syncthreads();
    }

    float* pb = part + ((size_t)(p * NSPLIT + s) * M) * NLOC;
#pragma unroll
    for (int i = 0; i < TM; ++i) {
        const int gm = bm0 + ty * 4 + (i & 3) + (i >> 2) * 64;
        if (gm >= M) continue;
#pragma unroll
        for (int j = 0; j < TP; ++j) {
            const int gn = bn0 + tx * 4 + j * 2;
            float c0v, c1v;
            UNPKF2(c0v, c1v, acc2[i][j]);
            *reinterpret_cast<float2*>(pb + (size_t)gm * NLOC + gn) =
                make_float2(c0v, c1v);
        }
    }
}

// reduce split-K partials + bias + sigmoid -> scatter into d_out e regions
__global__ void reduce_sig(const float* __restrict__ part,
                           const float* __restrict__ bias0,
                           const float* __restrict__ bias1,
                           float* __restrict__ out)
{
    const int m = blockIdx.x;
    const int p = blockIdx.y;
    const int n = threadIdx.x;
    float s = 0.0f;
#pragma unroll
    for (int sp = 0; sp < NSPLIT; ++sp)
        s += part[((size_t)(p * NSPLIT + sp) * M_TOT + m) * 256 + n];
    const float v = s + (p ? __ldg(bias1 + n) : __ldg(bias0 + n));
    const float r = 1.0f / (1.0f + expf(-v));
    float* dst = (m < N_R)
                     ? (out + (size_t)m * DFEAT + p * 256 + n)
                     : (out + EP_OFF + (size_t)(m - N_R) * DFEAT + p * 256 + n);
    *dst = r;
}

// ---------------------------------------------------------------------------
// CNN head — r10 version verbatim (conv1 smem-tap, conv2 4oc x 4ow FFMA2)
// ---------------------------------------------------------------------------
#define SMX    0
#define SMW1   (SMX  + 2 * 516)
#define SMB1   (SMW1 + 240)
#define SMB2   (SMB1 + 16)
#define SMW2   (SMB2 + 32)
#define SMP1   (SMW2 + 7680)
#define SMRED  (SMP1 + 16 * 2 * 260)
#define SMTOT  (SMRED + 16)

__global__ __launch_bounds__(256)
void conv_head_k(const float* __restrict__ w1, const float* __restrict__ b1,
                 const float* __restrict__ w2, const float* __restrict__ b2,
                 const int* __restrict__ idx,
                 const float* __restrict__ Wout, const float* __restrict__ bout,
                 float* __restrict__ out)
{
    extern __shared__ float smf[];
    float* s_x  = smf + SMX;
    float* s_w1 = smf + SMW1;
    float* s_b1 = smf + SMB1;
    float* s_b2 = smf + SMB2;
    float* s_w2 = smf + SMW2;
    float* s_p1 = smf + SMP1;
    float* s_red = smf + SMRED;

    const int tid = threadIdx.x;
    const int b   = blockIdx.x;

    for (int i = tid; i < 2 * 516; i += 256) s_x[i] = 0.0f;
    for (int i = tid; i < 16 * 2 * 260; i += 256) s_p1[i] = 0.0f;
    for (int i = tid; i < 240; i += 256) s_w1[i] = w1[i];
    for (int i = tid; i < 7680; i += 256) s_w2[i] = w2[i];
    if (tid < 16) s_b1[tid] = b1[tid];
    if (tid >= 32 && tid < 64) s_b2[tid - 32] = b2[tid - 32];

    const int id   = idx[b];
    const int r_no = id / 1512;
    const int p_no = id - r_no * 1512;
    __syncthreads();

    for (int c = tid; c < DFEAT; c += 256) {
        s_x[2 + c]        = out[(size_t)r_no * DFEAT + c];
        s_x[516 + 2 + c]  = out[EP_OFF + (size_t)p_no * DFEAT + c];
    }
    __syncthreads();

    for (int j = tid; j < 16 * 2 * 256; j += 256) {
        const int oc = j >> 9;
        const int ph = (j >> 8) & 1;
        const int pw = j & 255;
        const float* w = s_w1 + oc * 15;
        const float bv = s_b1[oc];
        float sum = 0.0f;
#pragma unroll
        for (int dh = 0; dh < 2; ++dh) {
            const int oh = 2 * ph + dh;
#pragma unroll
            for (int dw = 0; dw < 2; ++dw) {
                const int ow = 2 * pw + dw;
                float c = 0.0f;
#pragma unroll
                for (int kh = 0; kh < 3; ++kh) {
                    const int ih = oh + kh - 2;
                    if (ih >= 0 && ih < 2) {
#pragma unroll
                        for (int kw = 0; kw < 5; ++kw)
                            c = fmaf(w[kh * 5 + kw], s_x[ih * 516 + ow + kw], c);
                    }
                }
                c += bv;
                sum += (c >= 0.0f) ? c : 0.01f * c;
            }
        }
        s_p1[(oc * 2 + ph) * 260 + 2 + pw] = 0.25f * sum;
    }
    __syncthreads();

    float ro0 = 0.0f, ro1 = 0.0f;
#pragma unroll
    for (int pass = 0; pass < 4; ++pass) {
        const int t   = tid + pass * 256;
        const int ocg = t >> 7;
        const int ph  = (t >> 6) & 1;
        const int pwg = t & 63;
        const int ow0 = pwg * 4;

        ull accA2[4][2], accB2[4][2];
#pragma unroll
        for (int o = 0; o < 4; ++o) {
            accA2[o][0] = 0ULL; accA2[o][1] = 0ULL;
            accB2[o][0] = 0ULL; accB2[o][1] = 0ULL;
        }

        const int khA0 = 2 - 2 * ph;
#pragma unroll
        for (int ic = 0; ic < 16; ++ic) {
#pragma unroll
            for (int ih = 0; ih < 2; ++ih) {
                const float* rowp = s_p1 + (ic * 2 + ih) * 260;
                float4 u0 = *reinterpret_cast<const float4*>(rowp + ow0);
                float4 u1 = *reinterpret_cast<const float4*>(rowp + ow0 + 4);
                float in[8] = {u0.x, u0.y, u0.z, u0.w, u1.x, u1.y, u1.z, u1.w};
                ull p2[7];
#pragma unroll
                for (int s = 0; s < 7; ++s) PACKF2(p2[s], in[s], in[s + 1]);

                const int khA = ih + khA0;
                if (khA >= 0 && khA < 3) {
#pragma unroll
                    for (int o = 0; o < 4; ++o) {
                        const float* w = s_w2 + ((((ocg * 4 + o) * 16 + ic) * 3 + khA) * 5);
#pragma unroll
                        for (int kw = 0; kw < 5; ++kw) {
                            ull w2p; PACKF2(w2p, w[kw], w[kw]);
                            FMAF2(accA2[o][0], w2p, p2[kw]);
                            FMAF2(accA2[o][1], w2p, p2[kw + 2]);
                        }
                    }
                }
                const int khB = khA - 1;
                if (khB >= 0 && khB < 3) {
#pragma unroll
                    for (int o = 0; o < 4; ++o) {
                        const float* w = s_w2 + ((((ocg * 4 + o) * 16 + ic) * 3 + khB) * 5);
#pragma unroll
                        for (int kw = 0; kw < 5; ++kw) {
                            ull w2p; PACKF2(w2p, w[kw], w[kw]);
                            FMAF2(accB2[o][0], w2p, p2[kw]);
                            FMAF2(accB2[o][1], w2p, p2[kw + 2]);
                        }
                    }
                }
            }
        }
#pragma unroll
        for (int o = 0; o < 4; ++o) {
            const int oc = ocg * 4 + o;
            const float bv = s_b2[oc];
#pragma unroll
            for (int p = 0; p < 2; ++p) {
                float a0, a1, b0, b1;
                UNPKF2(a0, a1, accA2[o][p]);
                UNPKF2(b0, b1, accB2[o][p]);
                float m = fmaxf(fmaxf(a0, a1), fmaxf(b0, b1));
                float v = m + bv;
                v = (v >= 0.0f) ? v : 0.01f * v;
                float tv = tanhf(v);
                const int f = oc * 256 + ph * 128 + (pwg * 2 + p);
                out[FLAT_OFF + (size_t)b * 8192 + f] = tv;
                ro0 = fmaf(tv, Wout[2 * f], ro0);
                ro1 = fmaf(tv, Wout[2 * f + 1], ro1);
            }
        }
    }

#pragma unroll
    for (int off = 16; off > 0; off >>= 1) {
        ro0 += __shfl_down_sync(0xffffffffu, ro0, off);
        ro1 += __shfl_down_sync(0xffffffffu, ro1, off);
    }
    const int warp = tid >> 5, lane = tid & 31;
    if (lane == 0) { s_red[warp] = ro0; s_red[8 + warp] = ro1; }
    __syncthreads();
    if (tid == 0) {
        float a = 0.0f, c = 0.0f;
#pragma unroll
        for (int i = 0; i < 8; ++i) { a += s_red[i]; c += s_red[8 + i]; }
        out[OUT2_OFF + (size_t)b * 2 + 0] = a + bout[0];
        out[OUT2_OFF + (size_t)b * 2 + 1] = c + bout[1];
    }
}

// ---------------------------------------------------------------------------
extern "C" void kernel_launch(void* const* d_in, const int* in_sizes, int n_in,
                              void* d_out, int out_size)
{
    const float* r_att   = (const float*)d_in[0];
    const float* p_att   = (const float*)d_in[1];
    const float* r_fun   = (const float*)d_in[2];
    const float* p_fun   = (const float*)d_in[3];
    const int*   idx     = (const int*)  d_in[4];
    const float* W_att1  = (const float*)d_in[5];
    const float* b_att1  = (const float*)d_in[6];
    const float* W_att2  = (const float*)d_in[7];
    const float* b_att2  = (const float*)d_in[8];
    const float* W_fun1  = (const float*)d_in[9];
    const float* b_fun1  = (const float*)d_in[10];
    const float* W_fun2  = (const float*)d_in[11];
    const float* b_fun2  = (const float*)d_in[12];
    const float* conv1_w = (const float*)d_in[13];
    const float* conv1_b = (const float*)d_in[14];
    const float* conv2_w = (const float*)d_in[15];
    const float* conv2_b = (const float*)d_in[16];
    const float* W_out   = (const float*)d_in[17];
    const float* b_out   = (const float*)d_in[18];
    float* out = (float*)d_out;

    float *pAa, *pAf, *pHa, *pHf;
    cudaGetSymbolAddress((void**)&pAa, gAatt);
    cudaGetSymbolAddress((void**)&pAf, gAfun);
    cudaGetSymbolAddress((void**)&pHa, gHa);
    cudaGetSymbolAddress((void**)&pHf, gHf);

    const size_t conv_smem = SMTOT * sizeof(float);
    cudaFuncSetAttribute(conv_head_k, cudaFuncAttributeMaxDynamicSharedMemorySize,
                         (int)conv_smem);

    convA_f32<<<dim3((KP_FUN + 255) / 256, M_TOT), 256>>>(r_fun, p_fun, N_R, FUN_IN, KP_FUN, pAf);
    convA_f32<<<dim3((KP_ATT + 255) / 256, M_TOT), 256>>>(r_att, p_att, N_R, SIZE_R, KP_ATT, pAa);

    const int nby = (M_TOT + 127) / 128;   // 28

    // layer1 fused: att1 (16x28) + fun1 (32x28) = 1344 blocks
    sgemm_dual<128, 8><<<(ATT_H / 128 + FUN_H / 128) * nby, 256>>>(
        ATT_H / 128, FUN_H / 128, nby, M_TOT,
        pAa, KP_ATT, KP_ATT, SIZE_R, W_att1, ATT_H, b_att1, pHa, ATT_H,
        pAf, KP_FUN, KP_FUN, FUN_IN, W_fun1, FUN_H, b_fun1, pHf, FUN_H);

    // layer2 split-K: 2 problems x 4 splits x 4 x 28 = 896 blocks
    // (partials land in gAfun, which layer 1 has finished reading)
    sgemm_splitk<<<2 * NSPLIT * (256 / 64) * nby, 256>>>(
        nby, M_TOT, pAf,
        pHa, ATT_H, ATT_H, W_att2,
        pHf, FUN_H, FUN_H, W_fun2);

    reduce_sig<<<dim3(M_TOT, 2), 256>>>(pAf, b_att2, b_fun2, out);

    conv_head_k<<<BATCH, 256, conv_smem>>>(
        conv1_w, conv1_b, conv2_w, conv2_b, idx, W_out, b_out, out);

    (void)in_sizes; (void)n_in; (void)out_size;
}